// round 1
// baseline (speedup 1.0000x reference)
#include <cuda_runtime.h>
#include <math.h>

#define B_ 4
#define T_ 2048
#define E_ 1024
#define H_ 128
#define M_ (B_*T_)   // 8192

// Scratch for projections (allocation-free rule: use __device__ globals)
__device__ float g_q[M_*H_];
__device__ float g_k[M_*H_];
__device__ float g_v[M_*H_];

// ---------------------------------------------------------------------------
// QKV projection: out = x @ W + b  for (Wq,bq)->g_q, (Wk,bk)->g_k, (Wv,bv)->g_v
// Tiled GEMM: BM=64, BN=64, BK=32, 256 threads, 4x4 register micro-tile.
// ---------------------------------------------------------------------------
#define BM 64
#define BN 64
#define BK 32
#define XP 36   // Xs pitch (pad 32->36 floats: avoids 2-way conflict, keeps 16B align)

__global__ __launch_bounds__(256) void qkv_kernel(
    const float* __restrict__ x,
    const float* __restrict__ Wq, const float* __restrict__ bq,
    const float* __restrict__ Wk, const float* __restrict__ bk,
    const float* __restrict__ Wv, const float* __restrict__ bv)
{
    __shared__ float Xs[BM][XP];
    __shared__ float Ws[BK][BN];

    const float* W; const float* bias; float* out;
    if (blockIdx.z == 0)      { W = Wq; bias = bq; out = g_q; }
    else if (blockIdx.z == 1) { W = Wk; bias = bk; out = g_k; }
    else                      { W = Wv; bias = bv; out = g_v; }

    const int m0  = blockIdx.x * BM;
    const int n0  = blockIdx.y * BN;
    const int tid = threadIdx.x;
    const int tx  = tid & 15;
    const int ty  = tid >> 4;

    float acc[4][4] = {};

    for (int k0 = 0; k0 < E_; k0 += BK) {
        // load X tile 64x32 (512 float4)
        for (int i = tid; i < BM*BK/4; i += 256) {
            int r = i >> 3, c4 = i & 7;
            *(float4*)&Xs[r][c4*4] =
                *(const float4*)&x[(size_t)(m0 + r)*E_ + k0 + c4*4];
        }
        // load W tile 32x64 (512 float4)
        for (int i = tid; i < BK*BN/4; i += 256) {
            int r = i >> 4, c4 = i & 15;
            *(float4*)&Ws[r][c4*4] =
                *(const float4*)&W[(size_t)(k0 + r)*H_ + n0 + c4*4];
        }
        __syncthreads();

        #pragma unroll
        for (int kk = 0; kk < BK; kk++) {
            float a0 = Xs[ty*4+0][kk];
            float a1 = Xs[ty*4+1][kk];
            float a2 = Xs[ty*4+2][kk];
            float a3 = Xs[ty*4+3][kk];
            float4 b4 = *(float4*)&Ws[kk][tx*4];
            acc[0][0] += a0*b4.x; acc[0][1] += a0*b4.y; acc[0][2] += a0*b4.z; acc[0][3] += a0*b4.w;
            acc[1][0] += a1*b4.x; acc[1][1] += a1*b4.y; acc[1][2] += a1*b4.z; acc[1][3] += a1*b4.w;
            acc[2][0] += a2*b4.x; acc[2][1] += a2*b4.y; acc[2][2] += a2*b4.z; acc[2][3] += a2*b4.w;
            acc[3][0] += a3*b4.x; acc[3][1] += a3*b4.y; acc[3][2] += a3*b4.z; acc[3][3] += a3*b4.w;
        }
        __syncthreads();
    }

    float4 bias4 = *(const float4*)&bias[n0 + tx*4];
    #pragma unroll
    for (int i = 0; i < 4; i++) {
        float4 o;
        o.x = acc[i][0] + bias4.x;
        o.y = acc[i][1] + bias4.y;
        o.z = acc[i][2] + bias4.z;
        o.w = acc[i][3] + bias4.w;
        *(float4*)&out[(size_t)(m0 + ty*4 + i)*H_ + n0 + tx*4] = o;
    }
}

// ---------------------------------------------------------------------------
// Flash attention (causal, online softmax). Br=Bc=64, 256 threads.
// Thread (tx,ty), tx=tid&15, ty=tid>>4:
//   S micro-tile: rows ty*4+i (i<4), cols j*16+tx (j<4)      [conflict-free]
//   O micro-tile: rows ty*4+i (i<4), cols cc*16+tx (cc<8)    [conflict-free]
// ---------------------------------------------------------------------------
#define KP 132   // Ks pitch (floats): 128+4, keeps float4 align, phase-conflict-free
#define PP 65    // Ps pitch
#define SCALE 0.08838834764831845f   // 1/sqrt(128)

#define SMEM_FLOATS (64*128 + 64*KP + 64*128 + 64*PP)
#define SMEM_BYTES  (SMEM_FLOATS * 4)

__global__ __launch_bounds__(256) void attn_kernel(float* __restrict__ out)
{
    extern __shared__ float smem[];
    float* Qs = smem;                   // 64 x 128
    float* Ks = Qs + 64*128;            // 64 x KP
    float* Vs = Ks + 64*KP;             // 64 x 128
    float* Ps = Vs + 64*128;            // 64 x PP

    const int qt = blockIdx.x;          // q tile (0..31)
    const int b  = blockIdx.y;          // batch
    const int m0 = qt * 64;

    const float* qg = g_q + (size_t)b*T_*H_;
    const float* kg = g_k + (size_t)b*T_*H_;
    const float* vg = g_v + (size_t)b*T_*H_;

    const int tid = threadIdx.x;
    const int tx  = tid & 15;
    const int ty  = tid >> 4;
    const int row0 = ty * 4;            // local row base

    // load Q tile (64x128 = 2048 float4)
    for (int i = tid; i < 64*128/4; i += 256) {
        int r = i >> 5, c4 = i & 31;
        *(float4*)&Qs[r*128 + c4*4] =
            *(const float4*)&qg[(size_t)(m0 + r)*H_ + c4*4];
    }

    float m_i[4], l_i[4], O[4][8];
    #pragma unroll
    for (int i = 0; i < 4; i++) {
        m_i[i] = -1e30f; l_i[i] = 0.f;
        #pragma unroll
        for (int c = 0; c < 8; c++) O[i][c] = 0.f;
    }

    for (int j0 = 0; j0 <= m0; j0 += 64) {
        // load K,V tiles
        for (int i = tid; i < 64*128/4; i += 256) {
            int r = i >> 5, c4 = i & 31;
            *(float4*)&Ks[r*KP + c4*4] =
                *(const float4*)&kg[(size_t)(j0 + r)*H_ + c4*4];
            *(float4*)&Vs[r*128 + c4*4] =
                *(const float4*)&vg[(size_t)(j0 + r)*H_ + c4*4];
        }
        __syncthreads();

        // ---- S = Q @ K^T (micro 4x4, vectorized k-dim) ----
        float s[4][4] = {};
        #pragma unroll 4
        for (int k4 = 0; k4 < 32; k4++) {
            float4 a[4], kb[4];
            #pragma unroll
            for (int i = 0; i < 4; i++)
                a[i] = *(float4*)&Qs[(row0 + i)*128 + k4*4];
            #pragma unroll
            for (int j = 0; j < 4; j++)
                kb[j] = *(float4*)&Ks[(j*16 + tx)*KP + k4*4];
            #pragma unroll
            for (int i = 0; i < 4; i++)
                #pragma unroll
                for (int j = 0; j < 4; j++)
                    s[i][j] += a[i].x*kb[j].x + a[i].y*kb[j].y
                             + a[i].z*kb[j].z + a[i].w*kb[j].w;
        }

        // ---- online softmax (per-row over 64 cols; reduce across 16 lanes) ----
        #pragma unroll
        for (int i = 0; i < 4; i++) {
            const int grow = m0 + row0 + i;
            float v[4], rm = -1e30f;
            #pragma unroll
            for (int j = 0; j < 4; j++) {
                float val = s[i][j] * SCALE;
                if (j0 + j*16 + tx > grow) val = -1e30f;   // causal mask
                v[j] = val;
                rm = fmaxf(rm, val);
            }
            #pragma unroll
            for (int off = 8; off >= 1; off >>= 1)
                rm = fmaxf(rm, __shfl_xor_sync(0xffffffffu, rm, off));

            float m_new = fmaxf(m_i[i], rm);
            float alpha = __expf(m_i[i] - m_new);
            float rs = 0.f;
            #pragma unroll
            for (int j = 0; j < 4; j++) {
                float p = __expf(v[j] - m_new);
                Ps[(row0 + i)*PP + j*16 + tx] = p;
                rs += p;
            }
            #pragma unroll
            for (int off = 8; off >= 1; off >>= 1)
                rs += __shfl_xor_sync(0xffffffffu, rs, off);

            l_i[i] = l_i[i]*alpha + rs;
            m_i[i] = m_new;
            #pragma unroll
            for (int c = 0; c < 8; c++) O[i][c] *= alpha;
        }
        __syncthreads();

        // ---- O += P @ V ----
        #pragma unroll 4
        for (int jj = 0; jj < 64; jj++) {
            float pv[4];
            #pragma unroll
            for (int i = 0; i < 4; i++)
                pv[i] = Ps[(row0 + i)*PP + jj];
            float vv[8];
            #pragma unroll
            for (int c = 0; c < 8; c++)
                vv[c] = Vs[jj*128 + c*16 + tx];
            #pragma unroll
            for (int i = 0; i < 4; i++)
                #pragma unroll
                for (int c = 0; c < 8; c++)
                    O[i][c] += pv[i]*vv[c];
        }
        __syncthreads();   // K/V/P free for next iteration
    }

    // epilogue: normalize + write
    #pragma unroll
    for (int i = 0; i < 4; i++) {
        float inv = 1.0f / l_i[i];
        #pragma unroll
        for (int c = 0; c < 8; c++)
            out[((size_t)b*T_ + m0 + row0 + i)*H_ + c*16 + tx] = O[i][c] * inv;
    }
}

// ---------------------------------------------------------------------------
extern "C" void kernel_launch(void* const* d_in, const int* in_sizes, int n_in,
                              void* d_out, int out_size)
{
    const float* x  = (const float*)d_in[0];
    const float* Wq = (const float*)d_in[1];
    const float* bq = (const float*)d_in[2];
    const float* Wk = (const float*)d_in[3];
    const float* bk = (const float*)d_in[4];
    const float* Wv = (const float*)d_in[5];
    const float* bv = (const float*)d_in[6];
    float* out = (float*)d_out;

    dim3 g1(M_/BM, H_/BN, 3);
    qkv_kernel<<<g1, 256>>>(x, Wq, bq, Wk, bk, Wv, bv);

    cudaFuncSetAttribute(attn_kernel,
                         cudaFuncAttributeMaxDynamicSharedMemorySize, SMEM_BYTES);
    attn_kernel<<<dim3(T_/64, B_), 256, SMEM_BYTES>>>(out);
}

// round 2
// speedup vs baseline: 2.4158x; 2.4158x over previous
#include <cuda_runtime.h>

#define B_ 4
#define T_ 2048
#define E_ 1024
#define H_ 128
#define M_ (B_*T_)   // 8192

// Scratch (allocation-free rule: __device__ globals)
__device__ float g_q[M_*H_];
__device__ float g_k[M_*H_];
__device__ float g_v[M_*H_];

// ---------------------------------------------------------------------------
// tf32 helpers
// ---------------------------------------------------------------------------
__device__ __forceinline__ unsigned f2tf(float x) {
    unsigned y; asm("cvt.rna.tf32.f32 %0, %1;" : "=r"(y) : "f"(x)); return y;
}
__device__ __forceinline__ float f2tff(float x) { return __uint_as_float(f2tf(x)); }

// mma.m16n8k8 tf32: A row-major frag (4 regs), B col-major frag (2 regs), C f32 (4 regs)
__device__ __forceinline__ void mma_tf32(float d[4], const unsigned a[4], const unsigned b[2]) {
    asm volatile(
        "mma.sync.aligned.m16n8k8.row.col.f32.tf32.tf32.f32 "
        "{%0,%1,%2,%3}, {%4,%5,%6,%7}, {%8,%9}, {%0,%1,%2,%3};\n"
        : "+f"(d[0]), "+f"(d[1]), "+f"(d[2]), "+f"(d[3])
        : "r"(a[0]), "r"(a[1]), "r"(a[2]), "r"(a[3]), "r"(b[0]), "r"(b[1]));
}

// ---------------------------------------------------------------------------
// QKV projection: out = x @ W + b  (M=8192, N=128, K=1024), tf32 mma
// BM=128, BN=128, BK=32, 256 threads, warp grid 4(m) x 2(n), warp tile 32x64.
// ---------------------------------------------------------------------------
#define AP 36    // As pitch: (4g+tg) conflict-free
#define BP 136   // Bs pitch: (8tg+g) conflict-free

__global__ __launch_bounds__(256) void qkv_kernel(
    const float* __restrict__ x,
    const float* __restrict__ Wq, const float* __restrict__ bq,
    const float* __restrict__ Wk, const float* __restrict__ bk,
    const float* __restrict__ Wv, const float* __restrict__ bv)
{
    __shared__ float As[128*AP];   // 128 x 32 (pitch 36)
    __shared__ float Bs[32*BP];    // 32 x 128 (pitch 136)

    const float* W; const float* bias; float* out;
    if (blockIdx.y == 0)      { W = Wq; bias = bq; out = g_q; }
    else if (blockIdx.y == 1) { W = Wk; bias = bk; out = g_k; }
    else                      { W = Wv; bias = bv; out = g_v; }

    const int m0   = blockIdx.x * 128;
    const int tid  = threadIdx.x;
    const int w    = tid >> 5;
    const int lane = tid & 31;
    const int g    = lane >> 2;
    const int tg   = lane & 3;
    const int rb0  = (w & 3) * 32;   // warp row base
    const int cb   = (w >> 2) * 64;  // warp col base

    float acc[2][8][4];
    #pragma unroll
    for (int mt = 0; mt < 2; mt++)
        #pragma unroll
        for (int nt = 0; nt < 8; nt++)
            #pragma unroll
            for (int q = 0; q < 4; q++) acc[mt][nt][q] = 0.f;

    for (int k0 = 0; k0 < E_; k0 += 32) {
        // load A tile 128x32 (1024 float4, 4/thread), cvt to tf32
        #pragma unroll
        for (int t = 0; t < 4; t++) {
            int i = tid + t*256;
            int r = i >> 3, c4 = i & 7;
            float4 f = *(const float4*)&x[(size_t)(m0 + r)*E_ + k0 + c4*4];
            float* p = &As[r*AP + c4*4];
            p[0] = f2tff(f.x); p[1] = f2tff(f.y); p[2] = f2tff(f.z); p[3] = f2tff(f.w);
        }
        // load B tile 32x128 (1024 float4, 4/thread)
        #pragma unroll
        for (int t = 0; t < 4; t++) {
            int i = tid + t*256;
            int r = i >> 5, c4 = i & 31;
            float4 f = *(const float4*)&W[(size_t)(k0 + r)*H_ + c4*4];
            float* p = &Bs[r*BP + c4*4];
            p[0] = f2tff(f.x); p[1] = f2tff(f.y); p[2] = f2tff(f.z); p[3] = f2tff(f.w);
        }
        __syncthreads();

        #pragma unroll
        for (int ks = 0; ks < 4; ks++) {
            unsigned a[2][4];
            #pragma unroll
            for (int mt = 0; mt < 2; mt++) {
                int rr = rb0 + mt*16 + g;
                a[mt][0] = __float_as_uint(As[rr*AP     + ks*8 + tg]);
                a[mt][1] = __float_as_uint(As[(rr+8)*AP + ks*8 + tg]);
                a[mt][2] = __float_as_uint(As[rr*AP     + ks*8 + tg + 4]);
                a[mt][3] = __float_as_uint(As[(rr+8)*AP + ks*8 + tg + 4]);
            }
            #pragma unroll
            for (int nt = 0; nt < 8; nt++) {
                unsigned b[2];
                int cc = cb + nt*8 + g;
                b[0] = __float_as_uint(Bs[(ks*8 + tg  )*BP + cc]);
                b[1] = __float_as_uint(Bs[(ks*8 + tg+4)*BP + cc]);
                mma_tf32(acc[0][nt], a[0], b);
                mma_tf32(acc[1][nt], a[1], b);
            }
        }
        __syncthreads();
    }

    // epilogue: add bias, write (float2: cols 2tg, 2tg+1 contiguous)
    #pragma unroll
    for (int mt = 0; mt < 2; mt++) {
        #pragma unroll
        for (int r2 = 0; r2 < 2; r2++) {
            int row = m0 + rb0 + mt*16 + g + r2*8;
            #pragma unroll
            for (int nt = 0; nt < 8; nt++) {
                int col = cb + nt*8 + 2*tg;
                float2 o;
                o.x = acc[mt][nt][r2*2+0] + bias[col];
                o.y = acc[mt][nt][r2*2+1] + bias[col+1];
                *(float2*)&out[(size_t)row*H_ + col] = o;
            }
        }
    }
}

// ---------------------------------------------------------------------------
// Flash attention (causal) with tf32 mma.
// Br=128, Bc=64, H=128. 8 warps; warp w owns q-rows [w*16, w*16+16).
// S-GEMM: warp tile 16x64 (8 n8-tiles, 16 k-steps).
// PV-GEMM: warp tile 16x128 (16 n8-tiles, 8 k-steps).
// ---------------------------------------------------------------------------
#define QP 132   // (4g+tg) pattern
#define KP 132   // (4g+tg)
#define VP 136   // (8tg+g)
#define PP 68    // (4g+tg)
#define SCALE 0.08838834764831845f  // 1/sqrt(128)

#define ATT_SMEM_FLOATS (128*QP + 64*KP + 64*VP + 128*PP)
#define ATT_SMEM_BYTES  (ATT_SMEM_FLOATS * 4)

__global__ __launch_bounds__(256) void attn_kernel(float* __restrict__ out)
{
    extern __shared__ float sm[];
    float* Qs = sm;               // 128 x 128 (pitch 132)
    float* Ks = Qs + 128*QP;      // 64 x 128 (pitch 132)
    float* Vs = Ks + 64*KP;       // 64 x 128 (pitch 136)
    float* Ps = Vs + 64*VP;       // 128 x 64 (pitch 68)

    const int qt = blockIdx.x;
    const int bb = blockIdx.y;
    const int m0 = qt * 128;

    const float* qg = g_q + (size_t)bb*T_*H_;
    const float* kg = g_k + (size_t)bb*T_*H_;
    const float* vg = g_v + (size_t)bb*T_*H_;

    const int tid  = threadIdx.x;
    const int w    = tid >> 5;
    const int lane = tid & 31;
    const int g    = lane >> 2;
    const int tg   = lane & 3;
    const int rb   = w * 16;

    // load Q tile 128x128 (4096 float4, 16/thread), cvt tf32
    #pragma unroll
    for (int t = 0; t < 16; t++) {
        int i = tid + t*256;
        int r = i >> 5, c4 = i & 31;
        float4 f = *(const float4*)&qg[(size_t)(m0 + r)*H_ + c4*4];
        float* p = &Qs[r*QP + c4*4];
        p[0] = f2tff(f.x); p[1] = f2tff(f.y); p[2] = f2tff(f.z); p[3] = f2tff(f.w);
    }

    float o[16][4];
    #pragma unroll
    for (int nt = 0; nt < 16; nt++)
        #pragma unroll
        for (int q = 0; q < 4; q++) o[nt][q] = 0.f;
    float m_i[2] = {-1e30f, -1e30f};
    float l_i[2] = {0.f, 0.f};

    const int nTiles = 2*qt + 2;
    for (int jt = 0; jt < nTiles; jt++) {
        const int j0 = jt * 64;

        // load K,V tiles 64x128 (2048 float4 each, 8/thread each)
        #pragma unroll
        for (int t = 0; t < 8; t++) {
            int i = tid + t*256;
            int r = i >> 5, c4 = i & 31;
            float4 f = *(const float4*)&kg[(size_t)(j0 + r)*H_ + c4*4];
            float* p = &Ks[r*KP + c4*4];
            p[0] = f2tff(f.x); p[1] = f2tff(f.y); p[2] = f2tff(f.z); p[3] = f2tff(f.w);
            float4 fv = *(const float4*)&vg[(size_t)(j0 + r)*H_ + c4*4];
            float* pv = &Vs[r*VP + c4*4];
            pv[0] = f2tff(fv.x); pv[1] = f2tff(fv.y); pv[2] = f2tff(fv.z); pv[3] = f2tff(fv.w);
        }
        __syncthreads();

        // ---- S = Q @ K^T ----
        float s[8][4];
        #pragma unroll
        for (int nt = 0; nt < 8; nt++)
            #pragma unroll
            for (int q = 0; q < 4; q++) s[nt][q] = 0.f;

        #pragma unroll
        for (int ks = 0; ks < 16; ks++) {
            unsigned a[4];
            int rr = rb + g;
            a[0] = __float_as_uint(Qs[rr*QP     + ks*8 + tg]);
            a[1] = __float_as_uint(Qs[(rr+8)*QP + ks*8 + tg]);
            a[2] = __float_as_uint(Qs[rr*QP     + ks*8 + tg + 4]);
            a[3] = __float_as_uint(Qs[(rr+8)*QP + ks*8 + tg + 4]);
            #pragma unroll
            for (int nt = 0; nt < 8; nt++) {
                unsigned b[2];
                b[0] = __float_as_uint(Ks[(nt*8 + g)*KP + ks*8 + tg]);
                b[1] = __float_as_uint(Ks[(nt*8 + g)*KP + ks*8 + tg + 4]);
                mma_tf32(s[nt], a, b);
            }
        }

        // ---- online softmax (rows rb+g and rb+g+8, 4 lanes/row) ----
        const bool need_mask = (j0 + 64 > m0);
        #pragma unroll
        for (int r2 = 0; r2 < 2; r2++) {
            const int grow = m0 + rb + g + r2*8;
            float vv[8][2];
            float mloc = -1e30f;
            #pragma unroll
            for (int nt = 0; nt < 8; nt++) {
                float v0 = s[nt][r2*2+0] * SCALE;
                float v1 = s[nt][r2*2+1] * SCALE;
                if (need_mask) {
                    int c0 = j0 + nt*8 + 2*tg;
                    if (c0     > grow) v0 = -1e30f;
                    if (c0 + 1 > grow) v1 = -1e30f;
                }
                vv[nt][0] = v0; vv[nt][1] = v1;
                mloc = fmaxf(mloc, fmaxf(v0, v1));
            }
            mloc = fmaxf(mloc, __shfl_xor_sync(0xffffffffu, mloc, 1));
            mloc = fmaxf(mloc, __shfl_xor_sync(0xffffffffu, mloc, 2));
            float m_new = fmaxf(m_i[r2], mloc);
            float alpha = __expf(m_i[r2] - m_new);
            float rs = 0.f;
            #pragma unroll
            for (int nt = 0; nt < 8; nt++) {
                float p0 = __expf(vv[nt][0] - m_new);
                float p1 = __expf(vv[nt][1] - m_new);
                rs += p0 + p1;
                float2 pp;
                pp.x = f2tff(p0);
                pp.y = f2tff(p1);
                *(float2*)&Ps[(rb + g + r2*8)*PP + nt*8 + 2*tg] = pp;
            }
            rs += __shfl_xor_sync(0xffffffffu, rs, 1);
            rs += __shfl_xor_sync(0xffffffffu, rs, 2);
            l_i[r2] = l_i[r2]*alpha + rs;
            m_i[r2] = m_new;
            #pragma unroll
            for (int nt = 0; nt < 16; nt++) {
                o[nt][r2*2+0] *= alpha;
                o[nt][r2*2+1] *= alpha;
            }
        }
        __syncwarp();   // Ps rows are warp-private: warp-level fence suffices

        // ---- O += P @ V ----
        #pragma unroll
        for (int ks = 0; ks < 8; ks++) {
            unsigned a[4];
            int rr = rb + g;
            a[0] = __float_as_uint(Ps[rr*PP     + ks*8 + tg]);
            a[1] = __float_as_uint(Ps[(rr+8)*PP + ks*8 + tg]);
            a[2] = __float_as_uint(Ps[rr*PP     + ks*8 + tg + 4]);
            a[3] = __float_as_uint(Ps[(rr+8)*PP + ks*8 + tg + 4]);
            #pragma unroll
            for (int nt = 0; nt < 16; nt++) {
                unsigned b[2];
                b[0] = __float_as_uint(Vs[(ks*8 + tg  )*VP + nt*8 + g]);
                b[1] = __float_as_uint(Vs[(ks*8 + tg+4)*VP + nt*8 + g]);
                mma_tf32(o[nt], a, b);
            }
        }
        __syncthreads();   // all warps done with Ks/Vs before next load
    }

    // epilogue: normalize, write (float2)
    #pragma unroll
    for (int r2 = 0; r2 < 2; r2++) {
        float inv = 1.0f / l_i[r2];
        int row = m0 + rb + g + r2*8;
        #pragma unroll
        for (int nt = 0; nt < 16; nt++) {
            int col = nt*8 + 2*tg;
            float2 oo;
            oo.x = o[nt][r2*2+0] * inv;
            oo.y = o[nt][r2*2+1] * inv;
            *(float2*)&out[((size_t)bb*T_ + row)*H_ + col] = oo;
        }
    }
}

// ---------------------------------------------------------------------------
extern "C" void kernel_launch(void* const* d_in, const int* in_sizes, int n_in,
                              void* d_out, int out_size)
{
    const float* x  = (const float*)d_in[0];
    const float* Wq = (const float*)d_in[1];
    const float* bq = (const float*)d_in[2];
    const float* Wk = (const float*)d_in[3];
    const float* bk = (const float*)d_in[4];
    const float* Wv = (const float*)d_in[5];
    const float* bv = (const float*)d_in[6];
    float* out = (float*)d_out;

    qkv_kernel<<<dim3(M_/128, 3), 256>>>(x, Wq, bq, Wk, bk, Wv, bv);

    cudaFuncSetAttribute(attn_kernel,
                         cudaFuncAttributeMaxDynamicSharedMemorySize, ATT_SMEM_BYTES);
    attn_kernel<<<dim3(T_/128, B_), 256, ATT_SMEM_BYTES>>>(out);
}

// round 3
// speedup vs baseline: 3.9529x; 1.6362x over previous
#include <cuda_runtime.h>

#define B_ 4
#define T_ 2048
#define E_ 1024
#define H_ 128
#define M_ (B_*T_)   // 8192

// Scratch (allocation-free rule: __device__ globals)
__device__ float g_q[M_*H_];
__device__ float g_k[M_*H_];
__device__ float g_v[M_*H_];

// split-KV partials: 4 batches x 16 q-tiles x up to 4 chunks
// O partial: [part][128 rows][128 cols], m/l: [part][128 rows][2]
#define NPART (B_*16*4)
__device__ float g_po[NPART*128*128];   // 16 MB
__device__ float g_ml[NPART*128*2];

// chunk map: 34 (qt, chunk) pairs per batch (chunk = 10 Bc-tiles = 640 kv)
__constant__ int c_qt[34] = {0,1,2,3,4, 5,5,6,6,7,7,8,8,9,9,
                             10,10,10,11,11,11,12,12,12,13,13,13,14,14,14,
                             15,15,15,15};
__constant__ int c_ch[34] = {0,0,0,0,0, 0,1,0,1,0,1,0,1,0,1,
                             0,1,2,0,1,2,0,1,2,0,1,2,0,1,2,
                             0,1,2,3};
__constant__ int c_nch[16] = {1,1,1,1,1,2,2,2,2,2,3,3,3,3,3,4};

// ---------------------------------------------------------------------------
// tf32 helpers
// ---------------------------------------------------------------------------
__device__ __forceinline__ unsigned f2tf(float x) {
    unsigned y; asm("cvt.rna.tf32.f32 %0, %1;" : "=r"(y) : "f"(x)); return y;
}
__device__ __forceinline__ float f2tff(float x) { return __uint_as_float(f2tf(x)); }

__device__ __forceinline__ void mma_tf32(float d[4], const unsigned a[4], const unsigned b[2]) {
    asm volatile(
        "mma.sync.aligned.m16n8k8.row.col.f32.tf32.tf32.f32 "
        "{%0,%1,%2,%3}, {%4,%5,%6,%7}, {%8,%9}, {%0,%1,%2,%3};\n"
        : "+f"(d[0]), "+f"(d[1]), "+f"(d[2]), "+f"(d[3])
        : "r"(a[0]), "r"(a[1]), "r"(a[2]), "r"(a[3]), "r"(b[0]), "r"(b[1]));
}

// ---------------------------------------------------------------------------
// QKV projection (unchanged from R2): out = x @ W + b, tf32 mma
// ---------------------------------------------------------------------------
#define AP 36
#define BP 136

__global__ __launch_bounds__(256) void qkv_kernel(
    const float* __restrict__ x,
    const float* __restrict__ Wq, const float* __restrict__ bq,
    const float* __restrict__ Wk, const float* __restrict__ bk,
    const float* __restrict__ Wv, const float* __restrict__ bv)
{
    __shared__ float As[128*AP];
    __shared__ float Bs[32*BP];

    const float* W; const float* bias; float* out;
    if (blockIdx.y == 0)      { W = Wq; bias = bq; out = g_q; }
    else if (blockIdx.y == 1) { W = Wk; bias = bk; out = g_k; }
    else                      { W = Wv; bias = bv; out = g_v; }

    const int m0   = blockIdx.x * 128;
    const int tid  = threadIdx.x;
    const int w    = tid >> 5;
    const int lane = tid & 31;
    const int g    = lane >> 2;
    const int tg   = lane & 3;
    const int rb0  = (w & 3) * 32;
    const int cb   = (w >> 2) * 64;

    float acc[2][8][4];
    #pragma unroll
    for (int mt = 0; mt < 2; mt++)
        #pragma unroll
        for (int nt = 0; nt < 8; nt++)
            #pragma unroll
            for (int q = 0; q < 4; q++) acc[mt][nt][q] = 0.f;

    for (int k0 = 0; k0 < E_; k0 += 32) {
        #pragma unroll
        for (int t = 0; t < 4; t++) {
            int i = tid + t*256;
            int r = i >> 3, c4 = i & 7;
            float4 f = *(const float4*)&x[(size_t)(m0 + r)*E_ + k0 + c4*4];
            float* p = &As[r*AP + c4*4];
            p[0] = f2tff(f.x); p[1] = f2tff(f.y); p[2] = f2tff(f.z); p[3] = f2tff(f.w);
        }
        #pragma unroll
        for (int t = 0; t < 4; t++) {
            int i = tid + t*256;
            int r = i >> 5, c4 = i & 31;
            float4 f = *(const float4*)&W[(size_t)(k0 + r)*H_ + c4*4];
            float* p = &Bs[r*BP + c4*4];
            p[0] = f2tff(f.x); p[1] = f2tff(f.y); p[2] = f2tff(f.z); p[3] = f2tff(f.w);
        }
        __syncthreads();

        #pragma unroll
        for (int ks = 0; ks < 4; ks++) {
            unsigned a[2][4];
            #pragma unroll
            for (int mt = 0; mt < 2; mt++) {
                int rr = rb0 + mt*16 + g;
                a[mt][0] = __float_as_uint(As[rr*AP     + ks*8 + tg]);
                a[mt][1] = __float_as_uint(As[(rr+8)*AP + ks*8 + tg]);
                a[mt][2] = __float_as_uint(As[rr*AP     + ks*8 + tg + 4]);
                a[mt][3] = __float_as_uint(As[(rr+8)*AP + ks*8 + tg + 4]);
            }
            #pragma unroll
            for (int nt = 0; nt < 8; nt++) {
                unsigned b[2];
                int cc = cb + nt*8 + g;
                b[0] = __float_as_uint(Bs[(ks*8 + tg  )*BP + cc]);
                b[1] = __float_as_uint(Bs[(ks*8 + tg+4)*BP + cc]);
                mma_tf32(acc[0][nt], a[0], b);
                mma_tf32(acc[1][nt], a[1], b);
            }
        }
        __syncthreads();
    }

    #pragma unroll
    for (int mt = 0; mt < 2; mt++) {
        #pragma unroll
        for (int r2 = 0; r2 < 2; r2++) {
            int row = m0 + rb0 + mt*16 + g + r2*8;
            #pragma unroll
            for (int nt = 0; nt < 8; nt++) {
                int col = cb + nt*8 + 2*tg;
                float2 o;
                o.x = acc[mt][nt][r2*2+0] + bias[col];
                o.y = acc[mt][nt][r2*2+1] + bias[col+1];
                *(float2*)&out[(size_t)row*H_ + col] = o;
            }
        }
    }
}

// ---------------------------------------------------------------------------
// Split-KV flash attention (causal), tf32 mma.
// Br=128, Bc=64. Each CTA = (batch, q-tile, kv-chunk of <=10 Bc-tiles).
// Writes unnormalized partial O + per-row (m,l) to scratch.
// ---------------------------------------------------------------------------
#define QP 132
#define KP 132
#define VP 136
#define PP 68
#define SCALE 0.08838834764831845f  // 1/sqrt(128)
#define CHUNK_TILES 10

#define ATT_SMEM_FLOATS (128*QP + 64*KP + 64*VP + 128*PP)
#define ATT_SMEM_BYTES  (ATT_SMEM_FLOATS * 4)

__global__ __launch_bounds__(256) void attn_kernel()
{
    extern __shared__ float sm[];
    float* Qs = sm;
    float* Ks = Qs + 128*QP;
    float* Vs = Ks + 64*KP;
    float* Ps = Vs + 64*VP;

    const int qt = c_qt[blockIdx.x];
    const int ch = c_ch[blockIdx.x];
    const int bb = blockIdx.y;
    const int m0 = qt * 128;

    const int t0 = ch * CHUNK_TILES;
    const int nTiles = 2*qt + 2;
    const int t1 = (t0 + CHUNK_TILES < nTiles) ? t0 + CHUNK_TILES : nTiles;

    const float* qg = g_q + (size_t)bb*T_*H_;
    const float* kg = g_k + (size_t)bb*T_*H_;
    const float* vg = g_v + (size_t)bb*T_*H_;

    const int tid  = threadIdx.x;
    const int w    = tid >> 5;
    const int lane = tid & 31;
    const int g    = lane >> 2;
    const int tg   = lane & 3;
    const int rb   = w * 16;

    #pragma unroll
    for (int t = 0; t < 16; t++) {
        int i = tid + t*256;
        int r = i >> 5, c4 = i & 31;
        float4 f = *(const float4*)&qg[(size_t)(m0 + r)*H_ + c4*4];
        float* p = &Qs[r*QP + c4*4];
        p[0] = f2tff(f.x); p[1] = f2tff(f.y); p[2] = f2tff(f.z); p[3] = f2tff(f.w);
    }

    float o[16][4];
    #pragma unroll
    for (int nt = 0; nt < 16; nt++)
        #pragma unroll
        for (int q = 0; q < 4; q++) o[nt][q] = 0.f;
    float m_i[2] = {-1e30f, -1e30f};
    float l_i[2] = {0.f, 0.f};

    for (int jt = t0; jt < t1; jt++) {
        const int j0 = jt * 64;

        #pragma unroll
        for (int t = 0; t < 8; t++) {
            int i = tid + t*256;
            int r = i >> 5, c4 = i & 31;
            float4 f = *(const float4*)&kg[(size_t)(j0 + r)*H_ + c4*4];
            float* p = &Ks[r*KP + c4*4];
            p[0] = f2tff(f.x); p[1] = f2tff(f.y); p[2] = f2tff(f.z); p[3] = f2tff(f.w);
            float4 fv = *(const float4*)&vg[(size_t)(j0 + r)*H_ + c4*4];
            float* pv = &Vs[r*VP + c4*4];
            pv[0] = f2tff(fv.x); pv[1] = f2tff(fv.y); pv[2] = f2tff(fv.z); pv[3] = f2tff(fv.w);
        }
        __syncthreads();

        // ---- S = Q @ K^T ----
        float s[8][4];
        #pragma unroll
        for (int nt = 0; nt < 8; nt++)
            #pragma unroll
            for (int q = 0; q < 4; q++) s[nt][q] = 0.f;

        #pragma unroll
        for (int ks = 0; ks < 16; ks++) {
            unsigned a[4];
            int rr = rb + g;
            a[0] = __float_as_uint(Qs[rr*QP     + ks*8 + tg]);
            a[1] = __float_as_uint(Qs[(rr+8)*QP + ks*8 + tg]);
            a[2] = __float_as_uint(Qs[rr*QP     + ks*8 + tg + 4]);
            a[3] = __float_as_uint(Qs[(rr+8)*QP + ks*8 + tg + 4]);
            #pragma unroll
            for (int nt = 0; nt < 8; nt++) {
                unsigned b[2];
                b[0] = __float_as_uint(Ks[(nt*8 + g)*KP + ks*8 + tg]);
                b[1] = __float_as_uint(Ks[(nt*8 + g)*KP + ks*8 + tg + 4]);
                mma_tf32(s[nt], a, b);
            }
        }

        // ---- online softmax ----
        const bool need_mask = (j0 + 64 > m0);
        #pragma unroll
        for (int r2 = 0; r2 < 2; r2++) {
            const int grow = m0 + rb + g + r2*8;
            float vv[8][2];
            float mloc = -1e30f;
            #pragma unroll
            for (int nt = 0; nt < 8; nt++) {
                float v0 = s[nt][r2*2+0] * SCALE;
                float v1 = s[nt][r2*2+1] * SCALE;
                if (need_mask) {
                    int c0 = j0 + nt*8 + 2*tg;
                    if (c0     > grow) v0 = -1e30f;
                    if (c0 + 1 > grow) v1 = -1e30f;
                }
                vv[nt][0] = v0; vv[nt][1] = v1;
                mloc = fmaxf(mloc, fmaxf(v0, v1));
            }
            mloc = fmaxf(mloc, __shfl_xor_sync(0xffffffffu, mloc, 1));
            mloc = fmaxf(mloc, __shfl_xor_sync(0xffffffffu, mloc, 2));
            float m_new = fmaxf(m_i[r2], mloc);
            float alpha = __expf(m_i[r2] - m_new);
            float rs = 0.f;
            #pragma unroll
            for (int nt = 0; nt < 8; nt++) {
                float p0 = __expf(vv[nt][0] - m_new);
                float p1 = __expf(vv[nt][1] - m_new);
                rs += p0 + p1;
                float2 pp;
                pp.x = f2tff(p0);
                pp.y = f2tff(p1);
                *(float2*)&Ps[(rb + g + r2*8)*PP + nt*8 + 2*tg] = pp;
            }
            rs += __shfl_xor_sync(0xffffffffu, rs, 1);
            rs += __shfl_xor_sync(0xffffffffu, rs, 2);
            l_i[r2] = l_i[r2]*alpha + rs;
            m_i[r2] = m_new;
            #pragma unroll
            for (int nt = 0; nt < 16; nt++) {
                o[nt][r2*2+0] *= alpha;
                o[nt][r2*2+1] *= alpha;
            }
        }
        __syncwarp();

        // ---- O += P @ V ----
        #pragma unroll
        for (int ks = 0; ks < 8; ks++) {
            unsigned a[4];
            int rr = rb + g;
            a[0] = __float_as_uint(Ps[rr*PP     + ks*8 + tg]);
            a[1] = __float_as_uint(Ps[(rr+8)*PP + ks*8 + tg]);
            a[2] = __float_as_uint(Ps[rr*PP     + ks*8 + tg + 4]);
            a[3] = __float_as_uint(Ps[(rr+8)*PP + ks*8 + tg + 4]);
            #pragma unroll
            for (int nt = 0; nt < 16; nt++) {
                unsigned b[2];
                b[0] = __float_as_uint(Vs[(ks*8 + tg  )*VP + nt*8 + g]);
                b[1] = __float_as_uint(Vs[(ks*8 + tg+4)*VP + nt*8 + g]);
                mma_tf32(o[nt], a, b);
            }
        }
        __syncthreads();
    }

    // epilogue: write UNNORMALIZED partial + (m,l)
    const int part = (bb*16 + qt)*4 + ch;
    float* po = g_po + (size_t)part*16384;
    #pragma unroll
    for (int r2 = 0; r2 < 2; r2++) {
        int row = rb + g + r2*8;
        #pragma unroll
        for (int nt = 0; nt < 16; nt++) {
            int col = nt*8 + 2*tg;
            float2 oo;
            oo.x = o[nt][r2*2+0];
            oo.y = o[nt][r2*2+1];
            *(float2*)&po[row*128 + col] = oo;
        }
        if (tg == 0) {
            g_ml[part*256 + row*2    ] = m_i[r2];
            g_ml[part*256 + row*2 + 1] = l_i[r2];
        }
    }
}

// ---------------------------------------------------------------------------
// Merge: combine <=4 partials per (batch, q-tile), normalize, write out.
// ---------------------------------------------------------------------------
__global__ __launch_bounds__(256) void merge_kernel(float* __restrict__ out)
{
    const int qt = blockIdx.x;
    const int bb = blockIdx.y;
    const int nch = c_nch[qt];
    const int base = (bb*16 + qt)*4;

    __shared__ float ws[4][128];
    __shared__ float invd[128];

    const int tid = threadIdx.x;
    if (tid < 128) {
        float mv[4];
        float m_max = -1e30f;
        for (int c = 0; c < nch; c++) {
            mv[c] = g_ml[(base+c)*256 + tid*2];
            m_max = fmaxf(m_max, mv[c]);
        }
        float denom = 0.f;
        for (int c = 0; c < nch; c++) {
            float wv = __expf(mv[c] - m_max);
            ws[c][tid] = wv;
            denom += wv * g_ml[(base+c)*256 + tid*2 + 1];
        }
        invd[tid] = 1.0f / denom;
    }
    __syncthreads();

    #pragma unroll
    for (int it = 0; it < 16; it++) {
        int idx = tid + it*256;
        int row = idx >> 5, c4 = idx & 31;
        float4 acc = make_float4(0.f, 0.f, 0.f, 0.f);
        for (int c = 0; c < nch; c++) {
            float4 p = *(const float4*)&g_po[(size_t)(base+c)*16384 + row*128 + c4*4];
            float wv = ws[c][row];
            acc.x += wv*p.x; acc.y += wv*p.y; acc.z += wv*p.z; acc.w += wv*p.w;
        }
        float iv = invd[row];
        acc.x *= iv; acc.y *= iv; acc.z *= iv; acc.w *= iv;
        *(float4*)&out[((size_t)bb*T_ + qt*128 + row)*H_ + c4*4] = acc;
    }
}

// ---------------------------------------------------------------------------
extern "C" void kernel_launch(void* const* d_in, const int* in_sizes, int n_in,
                              void* d_out, int out_size)
{
    const float* x  = (const float*)d_in[0];
    const float* Wq = (const float*)d_in[1];
    const float* bq = (const float*)d_in[2];
    const float* Wk = (const float*)d_in[3];
    const float* bk = (const float*)d_in[4];
    const float* Wv = (const float*)d_in[5];
    const float* bv = (const float*)d_in[6];
    float* out = (float*)d_out;

    qkv_kernel<<<dim3(M_/128, 3), 256>>>(x, Wq, bq, Wk, bk, Wv, bv);

    cudaFuncSetAttribute(attn_kernel,
                         cudaFuncAttributeMaxDynamicSharedMemorySize, ATT_SMEM_BYTES);
    attn_kernel<<<dim3(34, B_), 256, ATT_SMEM_BYTES>>>();

    merge_kernel<<<dim3(16, B_), 256>>>(out);
}

// round 5
// speedup vs baseline: 6.7172x; 1.6993x over previous
#include <cuda_runtime.h>
#include <cuda_fp16.h>
#include <cstdint>

#define B_ 4
#define T_ 2048
#define E_ 1024
#define H_ 128
#define M_ (B_*T_)   // 8192

// ---------------------------------------------------------------------------
// Scratch (__device__ globals; allocation-free rule)
// ---------------------------------------------------------------------------
__device__ __half g_xh[M_*E_];       // x in fp16 (16 MB)
__device__ __half g_wh[3*E_*H_];     // Wq|Wk|Wv in fp16
__device__ __half g_q[M_*H_];
__device__ __half g_k[M_*H_];
__device__ __half g_v[M_*H_];

// split-KV partials
#define NPART (B_*16*4)
__device__ float g_po[NPART*128*128];   // 16 MB
__device__ float g_ml[NPART*128*2];

__constant__ int c_qt[34] = {0,1,2,3,4, 5,5,6,6,7,7,8,8,9,9,
                             10,10,10,11,11,11,12,12,12,13,13,13,14,14,14,
                             15,15,15,15};
__constant__ int c_ch[34] = {0,0,0,0,0, 0,1,0,1,0,1,0,1,0,1,
                             0,1,2,0,1,2,0,1,2,0,1,2,0,1,2,
                             0,1,2,3};
__constant__ int c_nch[16] = {1,1,1,1,1,2,2,2,2,2,3,3,3,3,3,4};

// ---------------------------------------------------------------------------
// PTX helpers
// ---------------------------------------------------------------------------
__device__ __forceinline__ unsigned smem_u32(const void* p) {
    return (unsigned)__cvta_generic_to_shared(p);
}
__device__ __forceinline__ void ldsm_x4(unsigned* r, unsigned a) {
    asm volatile("ldmatrix.sync.aligned.m8n8.x4.shared.b16 {%0,%1,%2,%3}, [%4];\n"
        : "=r"(r[0]), "=r"(r[1]), "=r"(r[2]), "=r"(r[3]) : "r"(a));
}
__device__ __forceinline__ void ldsm_x4_t(unsigned* r, unsigned a) {
    asm volatile("ldmatrix.sync.aligned.m8n8.x4.trans.shared.b16 {%0,%1,%2,%3}, [%4];\n"
        : "=r"(r[0]), "=r"(r[1]), "=r"(r[2]), "=r"(r[3]) : "r"(a));
}
__device__ __forceinline__ void mma_f16(float d[4], const unsigned a[4], const unsigned b[2]) {
    asm volatile(
        "mma.sync.aligned.m16n8k16.row.col.f32.f16.f16.f32 "
        "{%0,%1,%2,%3}, {%4,%5,%6,%7}, {%8,%9}, {%0,%1,%2,%3};\n"
        : "+f"(d[0]), "+f"(d[1]), "+f"(d[2]), "+f"(d[3])
        : "r"(a[0]), "r"(a[1]), "r"(a[2]), "r"(a[3]), "r"(b[0]), "r"(b[1]));
}
__device__ __forceinline__ void cp16(unsigned dst, const void* src) {
    asm volatile("cp.async.cg.shared.global [%0], [%1], 16;\n" :: "r"(dst), "l"(src));
}
__device__ __forceinline__ void cp_commit() { asm volatile("cp.async.commit_group;\n"); }
template<int N> __device__ __forceinline__ void cp_wait() {
    asm volatile("cp.async.wait_group %0;\n" :: "n"(N));
}
__device__ __forceinline__ unsigned packh2(float a, float b) {
    __half2 h = __floats2half2_rn(a, b);
    return *reinterpret_cast<unsigned*>(&h);
}

// ---------------------------------------------------------------------------
// Convert kernel: x, Wq/Wk/Wv -> fp16
// ---------------------------------------------------------------------------
__global__ __launch_bounds__(256) void convert_kernel(
    const float* __restrict__ x,
    const float* __restrict__ Wq, const float* __restrict__ Wk,
    const float* __restrict__ Wv)
{
    const int nth = gridDim.x * blockDim.x;
    const int i0  = blockIdx.x * blockDim.x + threadIdx.x;
    for (int i = i0; i < M_*E_/4; i += nth) {
        float4 f = ((const float4*)x)[i];
        ((__half2*)g_xh)[i*2]   = __floats2half2_rn(f.x, f.y);
        ((__half2*)g_xh)[i*2+1] = __floats2half2_rn(f.z, f.w);
    }
    const int WN = E_*H_/4;
    for (int i = i0; i < 3*WN; i += nth) {
        const float* W = (i < WN) ? Wq : (i < 2*WN ? Wk : Wv);
        int j = i - (i < WN ? 0 : (i < 2*WN ? WN : 2*WN));
        float4 f = ((const float4*)W)[j];
        ((__half2*)g_wh)[i*2]   = __floats2half2_rn(f.x, f.y);
        ((__half2*)g_wh)[i*2+1] = __floats2half2_rn(f.z, f.w);
    }
}

// ---------------------------------------------------------------------------
// QKV projection fp16: out = x @ W + b. BM=64, BN=128, BK=64.
// 8 warps in 4(m) x 2(n); warp tile 16 x 64. Double-buffered cp.async.
// As: [row][k] pitch 72 halves. Bs: [k][n] pitch 136 halves.
// ---------------------------------------------------------------------------
#define QKV_AP 72
#define QKV_BP 136
#define QKV_ABUF (64*QKV_AP)   // halves per buffer
#define QKV_BBUF (64*QKV_BP)
#define QKV_SMEM_BYTES ((2*QKV_ABUF + 2*QKV_BBUF)*2)

__global__ __launch_bounds__(256) void qkv_kernel(
    const float* __restrict__ bq, const float* __restrict__ bk,
    const float* __restrict__ bv)
{
    extern __shared__ __half smh[];
    __half* As = smh;                    // 2 x 64x72
    __half* Bs = smh + 2*QKV_ABUF;       // 2 x 64x136

    const int z = blockIdx.y;
    const float* bias = (z == 0) ? bq : (z == 1 ? bk : bv);
    __half* out = (z == 0) ? g_q : (z == 1 ? g_k : g_v);
    const __half* xh = g_xh;
    const __half* wh = g_wh + (size_t)z*E_*H_;

    const int m0   = blockIdx.x * 64;
    const int tid  = threadIdx.x;
    const int w    = tid >> 5;
    const int lane = tid & 31;
    const int g    = lane >> 2;
    const int tg   = lane & 3;
    const int lr   = lane & 7;
    const int seg  = lane >> 3;
    const int rb0  = (w & 3) * 16;
    const int cb   = (w >> 2) * 64;

    float acc[8][4];
    #pragma unroll
    for (int nt = 0; nt < 8; nt++)
        #pragma unroll
        for (int q = 0; q < 4; q++) acc[nt][q] = 0.f;

    auto load_tiles = [&](int it) {
        const int k0 = it * 64;
        #pragma unroll
        for (int t = 0; t < 2; t++) {
            int i = tid + t*256;
            int r = i >> 3, c = i & 7;
            cp16(smem_u32(&As[(it&1)*QKV_ABUF + r*QKV_AP + c*8]),
                 &xh[(size_t)(m0 + r)*E_ + k0 + c*8]);
        }
        #pragma unroll
        for (int t = 0; t < 4; t++) {
            int i = tid + t*256;
            int r = i >> 4, c = i & 15;
            cp16(smem_u32(&Bs[(it&1)*QKV_BBUF + r*QKV_BP + c*8]),
                 &wh[(size_t)(k0 + r)*H_ + c*8]);
        }
    };

    load_tiles(0);
    cp_commit();

    for (int it = 0; it < 16; it++) {
        if (it + 1 < 16) { load_tiles(it+1); cp_commit(); cp_wait<1>(); }
        else             { cp_wait<0>(); }
        __syncthreads();

        const __half* Ab = As + (it&1)*QKV_ABUF;
        const __half* Bb = Bs + (it&1)*QKV_BBUF;
        const unsigned abase = smem_u32(Ab) +
            ((rb0 + lr + (seg&1)*8)*QKV_AP + (seg>>1)*8)*2;
        const unsigned bbase = smem_u32(Bb) +
            (((seg&1)*8 + lr)*QKV_BP + cb + (seg>>1)*8)*2;

        #pragma unroll
        for (int ks = 0; ks < 4; ks++) {
            unsigned a[4];
            ldsm_x4(a, abase + ks*32);
            #pragma unroll
            for (int ntp = 0; ntp < 4; ntp++) {
                unsigned b[4];
                ldsm_x4_t(b, bbase + (ks*16*QKV_BP + ntp*16)*2);
                mma_f16(acc[ntp*2],   a, b);
                mma_f16(acc[ntp*2+1], a, b+2);
            }
        }
        __syncthreads();
    }

    #pragma unroll
    for (int r2 = 0; r2 < 2; r2++) {
        int row = m0 + rb0 + g + r2*8;
        #pragma unroll
        for (int nt = 0; nt < 8; nt++) {
            int col = cb + nt*8 + 2*tg;
            __half2 o = __floats2half2_rn(acc[nt][r2*2+0] + bias[col],
                                          acc[nt][r2*2+1] + bias[col+1]);
            *(__half2*)&out[(size_t)row*H_ + col] = o;
        }
    }
}

// ---------------------------------------------------------------------------
// Split-KV flash attention, fp16 mma, register-resident P, double-buffered K/V.
// Br=128, Bc=64. 8 warps; warp w owns q-rows [w*16, w*16+16).
// Qs: [row][hd] pitch 136. Ks/Vs: [pos][hd] pitch 136, 2 buffers each.
// ---------------------------------------------------------------------------
#define PH 136
#define QS_H   (128*PH)
#define KV_H   (64*PH)
#define ATT_SMEM_BYTES ((QS_H + 4*KV_H)*2)
#define SCALE 0.08838834764831845f  // 1/sqrt(128)
#define CHUNK_TILES 10

__global__ __launch_bounds__(256) void attn_kernel()
{
    extern __shared__ __half smh[];
    __half* Qs = smh;                 // 128 x 136
    __half* Ks = smh + QS_H;          // 2 x (64 x 136)
    __half* Vs = smh + QS_H + 2*KV_H; // 2 x (64 x 136)

    const int qt = c_qt[blockIdx.x];
    const int ch = c_ch[blockIdx.x];
    const int bb = blockIdx.y;
    const int m0 = qt * 128;

    const int t0 = ch * CHUNK_TILES;
    const int nTiles = 2*qt + 2;
    const int t1 = (t0 + CHUNK_TILES < nTiles) ? t0 + CHUNK_TILES : nTiles;

    const __half* qg = g_q + (size_t)bb*T_*H_;
    const __half* kg = g_k + (size_t)bb*T_*H_;
    const __half* vg = g_v + (size_t)bb*T_*H_;

    const int tid  = threadIdx.x;
    const int w    = tid >> 5;
    const int lane = tid & 31;
    const int g    = lane >> 2;
    const int tg   = lane & 3;
    const int lr   = lane & 7;
    const int seg  = lane >> 3;
    const int rb   = w * 16;

    auto load_kv = [&](int jt) {
        const int j0 = jt * 64;
        __half* Kd = Ks + (jt&1)*KV_H;
        __half* Vd = Vs + (jt&1)*KV_H;
        #pragma unroll
        for (int t = 0; t < 4; t++) {
            int i = tid + t*256;
            int r = i >> 4, c = i & 15;
            cp16(smem_u32(&Kd[r*PH + c*8]), &kg[(size_t)(j0 + r)*H_ + c*8]);
            cp16(smem_u32(&Vd[r*PH + c*8]), &vg[(size_t)(j0 + r)*H_ + c*8]);
        }
    };

    #pragma unroll
    for (int t = 0; t < 8; t++) {
        int i = tid + t*256;
        int r = i >> 4, c = i & 15;
        cp16(smem_u32(&Qs[r*PH + c*8]), &qg[(size_t)(m0 + r)*H_ + c*8]);
    }
    load_kv(t0);
    cp_commit();

    float o[16][4];
    #pragma unroll
    for (int nt = 0; nt < 16; nt++)
        #pragma unroll
        for (int q = 0; q < 4; q++) o[nt][q] = 0.f;
    float m_i[2] = {-1e30f, -1e30f};
    float l_i[2] = {0.f, 0.f};

    const unsigned qbase = smem_u32(Qs) + ((rb + lr + (seg&1)*8)*PH + (seg>>1)*8)*2;

    for (int jt = t0; jt < t1; jt++) {
        if (jt + 1 < t1) { load_kv(jt+1); cp_commit(); cp_wait<1>(); }
        else             { cp_wait<0>(); }
        __syncthreads();

        const __half* Kb = Ks + (jt&1)*KV_H;
        const __half* Vb = Vs + (jt&1)*KV_H;
        // K: [pos=n][hd=k], non-trans. rows n = ntp*16 + (seg>>1)*8 + lr; col k = ks*16 + (seg&1)*8
        const unsigned kbase = smem_u32(Kb) + (((seg>>1)*8 + lr)*PH + (seg&1)*8)*2;
        // V: [pos=k][hd=n], trans. rows k = ks*16 + (seg&1)*8 + lr; col n = ntp*16 + (seg>>1)*8
        const unsigned vbase = smem_u32(Vb) + (((seg&1)*8 + lr)*PH + (seg>>1)*8)*2;

        // ---- S = Q @ K^T ----
        float s[8][4];
        #pragma unroll
        for (int nt = 0; nt < 8; nt++)
            #pragma unroll
            for (int q = 0; q < 4; q++) s[nt][q] = 0.f;

        #pragma unroll
        for (int ks = 0; ks < 8; ks++) {
            unsigned a[4];
            ldsm_x4(a, qbase + ks*32);
            #pragma unroll
            for (int ntp = 0; ntp < 4; ntp++) {
                unsigned b[4];
                ldsm_x4(b, kbase + (ntp*16*PH)*2 + ks*32);
                mma_f16(s[ntp*2],   a, b);
                mma_f16(s[ntp*2+1], a, b+2);
            }
        }

        // ---- online softmax -> P packed in registers ----
        const int j0 = jt * 64;
        const bool need_mask = (j0 + 64 > m0);
        unsigned pp[8][2];
        #pragma unroll
        for (int r2 = 0; r2 < 2; r2++) {
            const int grow = m0 + rb + g + r2*8;
            float vv[8][2];
            float mloc = -1e30f;
            #pragma unroll
            for (int nt = 0; nt < 8; nt++) {
                float v0 = s[nt][r2*2+0] * SCALE;
                float v1 = s[nt][r2*2+1] * SCALE;
                if (need_mask) {
                    int c0 = j0 + nt*8 + 2*tg;
                    if (c0     > grow) v0 = -1e30f;
                    if (c0 + 1 > grow) v1 = -1e30f;
                }
                vv[nt][0] = v0; vv[nt][1] = v1;
                mloc = fmaxf(mloc, fmaxf(v0, v1));
            }
            mloc = fmaxf(mloc, __shfl_xor_sync(0xffffffffu, mloc, 1));
            mloc = fmaxf(mloc, __shfl_xor_sync(0xffffffffu, mloc, 2));
            float m_new = fmaxf(m_i[r2], mloc);
            float alpha = __expf(m_i[r2] - m_new);
            float rs = 0.f;
            #pragma unroll
            for (int nt = 0; nt < 8; nt++) {
                float p0 = __expf(vv[nt][0] - m_new);
                float p1 = __expf(vv[nt][1] - m_new);
                rs += p0 + p1;
                pp[nt][r2] = packh2(p0, p1);
            }
            rs += __shfl_xor_sync(0xffffffffu, rs, 1);
            rs += __shfl_xor_sync(0xffffffffu, rs, 2);
            l_i[r2] = l_i[r2]*alpha + rs;
            m_i[r2] = m_new;
            #pragma unroll
            for (int nt = 0; nt < 16; nt++) {
                o[nt][r2*2+0] *= alpha;
                o[nt][r2*2+1] *= alpha;
            }
        }

        // ---- O += P @ V (A from registers) ----
        #pragma unroll
        for (int ks = 0; ks < 4; ks++) {
            unsigned a[4] = { pp[2*ks][0], pp[2*ks][1], pp[2*ks+1][0], pp[2*ks+1][1] };
            #pragma unroll
            for (int ntp = 0; ntp < 8; ntp++) {
                unsigned b[4];
                ldsm_x4_t(b, vbase + (ks*16*PH + ntp*16)*2);
                mma_f16(o[ntp*2],   a, b);
                mma_f16(o[ntp*2+1], a, b+2);
            }
        }
        __syncthreads();   // all warps done with this K/V buffer
    }

    // epilogue: write UNNORMALIZED partial + (m,l)
    const int part = (bb*16 + qt)*4 + ch;
    float* po = g_po + (size_t)part*16384;
    #pragma unroll
    for (int r2 = 0; r2 < 2; r2++) {
        int row = rb + g + r2*8;
        #pragma unroll
        for (int nt = 0; nt < 16; nt++) {
            int col = nt*8 + 2*tg;
            float2 oo;
            oo.x = o[nt][r2*2+0];
            oo.y = o[nt][r2*2+1];
            *(float2*)&po[row*128 + col] = oo;
        }
        if (tg == 0) {
            g_ml[part*256 + row*2    ] = m_i[r2];
            g_ml[part*256 + row*2 + 1] = l_i[r2];
        }
    }
}

// ---------------------------------------------------------------------------
// Merge: combine <=4 partials per (batch, q-tile), normalize, write out.
// ---------------------------------------------------------------------------
__global__ __launch_bounds__(256) void merge_kernel(float* __restrict__ out)
{
    const int qt = blockIdx.x;
    const int bb = blockIdx.y;
    const int nch = c_nch[qt];
    const int base = (bb*16 + qt)*4;

    __shared__ float ws[4][128];
    __shared__ float invd[128];

    const int tid = threadIdx.x;
    if (tid < 128) {
        float mv[4];
        float m_max = -1e30f;
        for (int c = 0; c < nch; c++) {
            mv[c] = g_ml[(base+c)*256 + tid*2];
            m_max = fmaxf(m_max, mv[c]);
        }
        float denom = 0.f;
        for (int c = 0; c < nch; c++) {
            float wv = __expf(mv[c] - m_max);
            ws[c][tid] = wv;
            denom += wv * g_ml[(base+c)*256 + tid*2 + 1];
        }
        invd[tid] = 1.0f / denom;
    }
    __syncthreads();

    #pragma unroll
    for (int it = 0; it < 16; it++) {
        int idx = tid + it*256;
        int row = idx >> 5, c4 = idx & 31;
        float4 acc = make_float4(0.f, 0.f, 0.f, 0.f);
        for (int c = 0; c < nch; c++) {
            float4 p = *(const float4*)&g_po[(size_t)(base+c)*16384 + row*128 + c4*4];
            float wv = ws[c][row];
            acc.x += wv*p.x; acc.y += wv*p.y; acc.z += wv*p.z; acc.w += wv*p.w;
        }
        float iv = invd[row];
        acc.x *= iv; acc.y *= iv; acc.z *= iv; acc.w *= iv;
        *(float4*)&out[((size_t)bb*T_ + qt*128 + row)*H_ + c4*4] = acc;
    }
}

// ---------------------------------------------------------------------------
extern "C" void kernel_launch(void* const* d_in, const int* in_sizes, int n_in,
                              void* d_out, int out_size)
{
    const float* x  = (const float*)d_in[0];
    const float* Wq = (const float*)d_in[1];
    const float* bq = (const float*)d_in[2];
    const float* Wk = (const float*)d_in[3];
    const float* bk = (const float*)d_in[4];
    const float* Wv = (const float*)d_in[5];
    const float* bv = (const float*)d_in[6];
    float* out = (float*)d_out;

    convert_kernel<<<1024, 256>>>(x, Wq, Wk, Wv);

    cudaFuncSetAttribute(qkv_kernel,
                         cudaFuncAttributeMaxDynamicSharedMemorySize, QKV_SMEM_BYTES);
    qkv_kernel<<<dim3(M_/64, 3), 256, QKV_SMEM_BYTES>>>(bq, bk, bv);

    cudaFuncSetAttribute(attn_kernel,
                         cudaFuncAttributeMaxDynamicSharedMemorySize, ATT_SMEM_BYTES);
    attn_kernel<<<dim3(34, B_), 256, ATT_SMEM_BYTES>>>();

    merge_kernel<<<dim3(16, B_), 256>>>(out);
}

// round 6
// speedup vs baseline: 7.5132x; 1.1185x over previous
#include <cuda_runtime.h>
#include <cuda_fp16.h>
#include <cstdint>

#define B_ 4
#define T_ 2048
#define E_ 1024
#define H_ 128
#define M_ (B_*T_)   // 8192

// ---------------------------------------------------------------------------
// Scratch (__device__ globals; allocation-free rule)
// ---------------------------------------------------------------------------
__device__ __half g_xh[M_*E_];       // x in fp16 (16 MB)
__device__ __half g_wh[3*E_*H_];     // Wq|Wk|Wv in fp16
__device__ __half g_q[M_*H_];
__device__ __half g_k[M_*H_];
__device__ __half g_v[M_*H_];

// split-KV partials (only used for q-tiles with >1 chunk)
#define NPART (B_*16*4)
__device__ float g_po[NPART*128*128];   // 16 MB
__device__ float g_ml[NPART*128*2];

__constant__ int c_qt[34] = {0,1,2,3,4, 5,5,6,6,7,7,8,8,9,9,
                             10,10,10,11,11,11,12,12,12,13,13,13,14,14,14,
                             15,15,15,15};
__constant__ int c_ch[34] = {0,0,0,0,0, 0,1,0,1,0,1,0,1,0,1,
                             0,1,2,0,1,2,0,1,2,0,1,2,0,1,2,
                             0,1,2,3};
__constant__ int c_nch[16] = {1,1,1,1,1,2,2,2,2,2,3,3,3,3,3,4};

// ---------------------------------------------------------------------------
// PTX helpers
// ---------------------------------------------------------------------------
__device__ __forceinline__ unsigned smem_u32(const void* p) {
    return (unsigned)__cvta_generic_to_shared(p);
}
__device__ __forceinline__ void ldsm_x4(unsigned* r, unsigned a) {
    asm volatile("ldmatrix.sync.aligned.m8n8.x4.shared.b16 {%0,%1,%2,%3}, [%4];\n"
        : "=r"(r[0]), "=r"(r[1]), "=r"(r[2]), "=r"(r[3]) : "r"(a));
}
__device__ __forceinline__ void ldsm_x4_t(unsigned* r, unsigned a) {
    asm volatile("ldmatrix.sync.aligned.m8n8.x4.trans.shared.b16 {%0,%1,%2,%3}, [%4];\n"
        : "=r"(r[0]), "=r"(r[1]), "=r"(r[2]), "=r"(r[3]) : "r"(a));
}
__device__ __forceinline__ void mma_f16(float d[4], const unsigned a[4], const unsigned b[2]) {
    asm volatile(
        "mma.sync.aligned.m16n8k16.row.col.f32.f16.f16.f32 "
        "{%0,%1,%2,%3}, {%4,%5,%6,%7}, {%8,%9}, {%0,%1,%2,%3};\n"
        : "+f"(d[0]), "+f"(d[1]), "+f"(d[2]), "+f"(d[3])
        : "r"(a[0]), "r"(a[1]), "r"(a[2]), "r"(a[3]), "r"(b[0]), "r"(b[1]));
}
__device__ __forceinline__ void cp16(unsigned dst, const void* src) {
    asm volatile("cp.async.cg.shared.global [%0], [%1], 16;\n" :: "r"(dst), "l"(src));
}
__device__ __forceinline__ void cp_commit() { asm volatile("cp.async.commit_group;\n"); }
template<int N> __device__ __forceinline__ void cp_wait() {
    asm volatile("cp.async.wait_group %0;\n" :: "n"(N));
}
__device__ __forceinline__ unsigned packh2(float a, float b) {
    __half2 h = __floats2half2_rn(a, b);
    return *reinterpret_cast<unsigned*>(&h);
}

// ---------------------------------------------------------------------------
// Convert kernel: x, Wq/Wk/Wv -> fp16
// ---------------------------------------------------------------------------
__global__ __launch_bounds__(256) void convert_kernel(
    const float* __restrict__ x,
    const float* __restrict__ Wq, const float* __restrict__ Wk,
    const float* __restrict__ Wv)
{
    const int nth = gridDim.x * blockDim.x;
    const int i0  = blockIdx.x * blockDim.x + threadIdx.x;
    for (int i = i0; i < M_*E_/4; i += nth) {
        float4 f = ((const float4*)x)[i];
        ((__half2*)g_xh)[i*2]   = __floats2half2_rn(f.x, f.y);
        ((__half2*)g_xh)[i*2+1] = __floats2half2_rn(f.z, f.w);
    }
    const int WN = E_*H_/4;
    for (int i = i0; i < 3*WN; i += nth) {
        const float* W = (i < WN) ? Wq : (i < 2*WN ? Wk : Wv);
        int j = i - (i < WN ? 0 : (i < 2*WN ? WN : 2*WN));
        float4 f = ((const float4*)W)[j];
        ((__half2*)g_wh)[i*2]   = __floats2half2_rn(f.x, f.y);
        ((__half2*)g_wh)[i*2+1] = __floats2half2_rn(f.z, f.w);
    }
}

// ---------------------------------------------------------------------------
// QKV projection fp16: out = x @ W + b. BM=64, BN=128, BK=64.
// 8 warps in 4(m) x 2(n); warp tile 16 x 64. Double-buffered cp.async.
// ---------------------------------------------------------------------------
#define QKV_AP 72
#define QKV_BP 136
#define QKV_ABUF (64*QKV_AP)
#define QKV_BBUF (64*QKV_BP)
#define QKV_SMEM_BYTES ((2*QKV_ABUF + 2*QKV_BBUF)*2)

__global__ __launch_bounds__(256) void qkv_kernel(
    const float* __restrict__ bq, const float* __restrict__ bk,
    const float* __restrict__ bv)
{
    extern __shared__ __half smh[];
    __half* As = smh;                    // 2 x 64x72
    __half* Bs = smh + 2*QKV_ABUF;       // 2 x 64x136

    const int z = blockIdx.y;
    const float* bias = (z == 0) ? bq : (z == 1 ? bk : bv);
    __half* out = (z == 0) ? g_q : (z == 1 ? g_k : g_v);
    const __half* xh = g_xh;
    const __half* wh = g_wh + (size_t)z*E_*H_;

    const int m0   = blockIdx.x * 64;
    const int tid  = threadIdx.x;
    const int w    = tid >> 5;
    const int lane = tid & 31;
    const int g    = lane >> 2;
    const int tg   = lane & 3;
    const int lr   = lane & 7;
    const int seg  = lane >> 3;
    const int rb0  = (w & 3) * 16;
    const int cb   = (w >> 2) * 64;

    float acc[8][4];
    #pragma unroll
    for (int nt = 0; nt < 8; nt++)
        #pragma unroll
        for (int q = 0; q < 4; q++) acc[nt][q] = 0.f;

    auto load_tiles = [&](int it) {
        const int k0 = it * 64;
        #pragma unroll
        for (int t = 0; t < 2; t++) {
            int i = tid + t*256;
            int r = i >> 3, c = i & 7;
            cp16(smem_u32(&As[(it&1)*QKV_ABUF + r*QKV_AP + c*8]),
                 &xh[(size_t)(m0 + r)*E_ + k0 + c*8]);
        }
        #pragma unroll
        for (int t = 0; t < 4; t++) {
            int i = tid + t*256;
            int r = i >> 4, c = i & 15;
            cp16(smem_u32(&Bs[(it&1)*QKV_BBUF + r*QKV_BP + c*8]),
                 &wh[(size_t)(k0 + r)*H_ + c*8]);
        }
    };

    load_tiles(0);
    cp_commit();

    for (int it = 0; it < 16; it++) {
        if (it + 1 < 16) { load_tiles(it+1); cp_commit(); cp_wait<1>(); }
        else             { cp_wait<0>(); }
        __syncthreads();

        const __half* Ab = As + (it&1)*QKV_ABUF;
        const __half* Bb = Bs + (it&1)*QKV_BBUF;
        const unsigned abase = smem_u32(Ab) +
            ((rb0 + lr + (seg&1)*8)*QKV_AP + (seg>>1)*8)*2;
        const unsigned bbase = smem_u32(Bb) +
            (((seg&1)*8 + lr)*QKV_BP + cb + (seg>>1)*8)*2;

        #pragma unroll
        for (int ks = 0; ks < 4; ks++) {
            unsigned a[4];
            ldsm_x4(a, abase + ks*32);
            #pragma unroll
            for (int ntp = 0; ntp < 4; ntp++) {
                unsigned b[4];
                ldsm_x4_t(b, bbase + (ks*16*QKV_BP + ntp*16)*2);
                mma_f16(acc[ntp*2],   a, b);
                mma_f16(acc[ntp*2+1], a, b+2);
            }
        }
        __syncthreads();
    }

    #pragma unroll
    for (int r2 = 0; r2 < 2; r2++) {
        int row = m0 + rb0 + g + r2*8;
        #pragma unroll
        for (int nt = 0; nt < 8; nt++) {
            int col = cb + nt*8 + 2*tg;
            __half2 o = __floats2half2_rn(acc[nt][r2*2+0] + bias[col],
                                          acc[nt][r2*2+1] + bias[col+1]);
            *(__half2*)&out[(size_t)row*H_ + col] = o;
        }
    }
}

// ---------------------------------------------------------------------------
// Split-KV flash attention, fp16 mma, register-resident P, double-buffered K/V.
// Br=128, Bc=64. nch==1 tiles write final output directly (skip merge).
// ---------------------------------------------------------------------------
#define PH 136
#define QS_H   (128*PH)
#define KV_H   (64*PH)
#define ATT_SMEM_BYTES ((QS_H + 4*KV_H)*2)
#define SCALE 0.08838834764831845f  // 1/sqrt(128)

__global__ __launch_bounds__(256) void attn_kernel(float* __restrict__ outp)
{
    extern __shared__ __half smh[];
    __half* Qs = smh;                 // 128 x 136
    __half* Ks = smh + QS_H;          // 2 x (64 x 136)
    __half* Vs = smh + QS_H + 2*KV_H; // 2 x (64 x 136)

    const int qt = c_qt[blockIdx.x];
    const int ch = c_ch[blockIdx.x];
    const int bb = blockIdx.y;
    const int m0 = qt * 128;

    // even-split chunk bounds
    const int nTiles = 2*qt + 2;
    const int nch = c_nch[qt];
    const int bsz = nTiles / nch, rem = nTiles % nch;
    const int t0 = ch*bsz + (ch < rem ? ch : rem);
    const int t1 = t0 + bsz + (ch < rem ? 1 : 0);

    const __half* qg = g_q + (size_t)bb*T_*H_;
    const __half* kg = g_k + (size_t)bb*T_*H_;
    const __half* vg = g_v + (size_t)bb*T_*H_;

    const int tid  = threadIdx.x;
    const int w    = tid >> 5;
    const int lane = tid & 31;
    const int g    = lane >> 2;
    const int tg   = lane & 3;
    const int lr   = lane & 7;
    const int seg  = lane >> 3;
    const int rb   = w * 16;

    auto load_kv = [&](int jt) {
        const int j0 = jt * 64;
        __half* Kd = Ks + (jt&1)*KV_H;
        __half* Vd = Vs + (jt&1)*KV_H;
        #pragma unroll
        for (int t = 0; t < 4; t++) {
            int i = tid + t*256;
            int r = i >> 4, c = i & 15;
            cp16(smem_u32(&Kd[r*PH + c*8]), &kg[(size_t)(j0 + r)*H_ + c*8]);
            cp16(smem_u32(&Vd[r*PH + c*8]), &vg[(size_t)(j0 + r)*H_ + c*8]);
        }
    };

    #pragma unroll
    for (int t = 0; t < 8; t++) {
        int i = tid + t*256;
        int r = i >> 4, c = i & 15;
        cp16(smem_u32(&Qs[r*PH + c*8]), &qg[(size_t)(m0 + r)*H_ + c*8]);
    }
    load_kv(t0);
    cp_commit();

    float o[16][4];
    #pragma unroll
    for (int nt = 0; nt < 16; nt++)
        #pragma unroll
        for (int q = 0; q < 4; q++) o[nt][q] = 0.f;
    float m_i[2] = {-1e30f, -1e30f};
    float l_i[2] = {0.f, 0.f};

    const unsigned qbase = smem_u32(Qs) + ((rb + lr + (seg&1)*8)*PH + (seg>>1)*8)*2;

    for (int jt = t0; jt < t1; jt++) {
        if (jt + 1 < t1) { load_kv(jt+1); cp_commit(); cp_wait<1>(); }
        else             { cp_wait<0>(); }
        __syncthreads();

        const __half* Kb = Ks + (jt&1)*KV_H;
        const __half* Vb = Vs + (jt&1)*KV_H;
        const unsigned kbase = smem_u32(Kb) + (((seg>>1)*8 + lr)*PH + (seg&1)*8)*2;
        const unsigned vbase = smem_u32(Vb) + (((seg&1)*8 + lr)*PH + (seg>>1)*8)*2;

        // ---- S = Q @ K^T ----
        float s[8][4];
        #pragma unroll
        for (int nt = 0; nt < 8; nt++)
            #pragma unroll
            for (int q = 0; q < 4; q++) s[nt][q] = 0.f;

        #pragma unroll
        for (int ks = 0; ks < 8; ks++) {
            unsigned a[4];
            ldsm_x4(a, qbase + ks*32);
            #pragma unroll
            for (int ntp = 0; ntp < 4; ntp++) {
                unsigned b[4];
                ldsm_x4(b, kbase + (ntp*16*PH)*2 + ks*32);
                mma_f16(s[ntp*2],   a, b);
                mma_f16(s[ntp*2+1], a, b+2);
            }
        }

        // ---- online softmax -> P packed in registers ----
        const int j0 = jt * 64;
        const bool need_mask = (j0 + 64 > m0);
        unsigned pp[8][2];
        #pragma unroll
        for (int r2 = 0; r2 < 2; r2++) {
            const int grow = m0 + rb + g + r2*8;
            float vv[8][2];
            float mloc = -1e30f;
            #pragma unroll
            for (int nt = 0; nt < 8; nt++) {
                float v0 = s[nt][r2*2+0] * SCALE;
                float v1 = s[nt][r2*2+1] * SCALE;
                if (need_mask) {
                    int c0 = j0 + nt*8 + 2*tg;
                    if (c0     > grow) v0 = -1e30f;
                    if (c0 + 1 > grow) v1 = -1e30f;
                }
                vv[nt][0] = v0; vv[nt][1] = v1;
                mloc = fmaxf(mloc, fmaxf(v0, v1));
            }
            mloc = fmaxf(mloc, __shfl_xor_sync(0xffffffffu, mloc, 1));
            mloc = fmaxf(mloc, __shfl_xor_sync(0xffffffffu, mloc, 2));
            float m_new = fmaxf(m_i[r2], mloc);
            float alpha = __expf(m_i[r2] - m_new);
            float rs = 0.f;
            #pragma unroll
            for (int nt = 0; nt < 8; nt++) {
                float p0 = __expf(vv[nt][0] - m_new);
                float p1 = __expf(vv[nt][1] - m_new);
                rs += p0 + p1;
                pp[nt][r2] = packh2(p0, p1);
            }
            rs += __shfl_xor_sync(0xffffffffu, rs, 1);
            rs += __shfl_xor_sync(0xffffffffu, rs, 2);
            l_i[r2] = l_i[r2]*alpha + rs;
            m_i[r2] = m_new;
            #pragma unroll
            for (int nt = 0; nt < 16; nt++) {
                o[nt][r2*2+0] *= alpha;
                o[nt][r2*2+1] *= alpha;
            }
        }

        // ---- O += P @ V (A from registers) ----
        #pragma unroll
        for (int ks = 0; ks < 4; ks++) {
            unsigned a[4] = { pp[2*ks][0], pp[2*ks][1], pp[2*ks+1][0], pp[2*ks+1][1] };
            #pragma unroll
            for (int ntp = 0; ntp < 8; ntp++) {
                unsigned b[4];
                ldsm_x4_t(b, vbase + (ks*16*PH + ntp*16)*2);
                mma_f16(o[ntp*2],   a, b);
                mma_f16(o[ntp*2+1], a, b+2);
            }
        }
        __syncthreads();
    }

    if (nch == 1) {
        // single chunk: normalize and write final output directly
        float* og = outp + ((size_t)bb*T_ + m0)*H_;
        #pragma unroll
        for (int r2 = 0; r2 < 2; r2++) {
            float inv = 1.0f / l_i[r2];
            int row = rb + g + r2*8;
            #pragma unroll
            for (int nt = 0; nt < 16; nt++) {
                int col = nt*8 + 2*tg;
                float2 oo;
                oo.x = o[nt][r2*2+0] * inv;
                oo.y = o[nt][r2*2+1] * inv;
                *(float2*)&og[(size_t)row*H_ + col] = oo;
            }
        }
    } else {
        // write UNNORMALIZED partial + (m,l)
        const int part = (bb*16 + qt)*4 + ch;
        float* po = g_po + (size_t)part*16384;
        #pragma unroll
        for (int r2 = 0; r2 < 2; r2++) {
            int row = rb + g + r2*8;
            #pragma unroll
            for (int nt = 0; nt < 16; nt++) {
                int col = nt*8 + 2*tg;
                float2 oo;
                oo.x = o[nt][r2*2+0];
                oo.y = o[nt][r2*2+1];
                *(float2*)&po[row*128 + col] = oo;
            }
            if (tg == 0) {
                g_ml[part*256 + row*2    ] = m_i[r2];
                g_ml[part*256 + row*2 + 1] = l_i[r2];
            }
        }
    }
}

// ---------------------------------------------------------------------------
// Merge: combine partials for q-tiles 5..15. grid (11, B, 4 row-splits).
// ---------------------------------------------------------------------------
__global__ __launch_bounds__(256) void merge_kernel(float* __restrict__ out)
{
    const int qt = 5 + blockIdx.x;
    const int bb = blockIdx.y;
    const int r0 = blockIdx.z * 32;
    const int nch = c_nch[qt];
    const int base = (bb*16 + qt)*4;

    __shared__ float ws[4][32];
    __shared__ float invd[32];

    const int tid = threadIdx.x;
    if (tid < 32) {
        int row = r0 + tid;
        float mv[4];
        float m_max = -1e30f;
        for (int c = 0; c < nch; c++) {
            mv[c] = g_ml[(base+c)*256 + row*2];
            m_max = fmaxf(m_max, mv[c]);
        }
        float denom = 0.f;
        for (int c = 0; c < nch; c++) {
            float wv = __expf(mv[c] - m_max);
            ws[c][tid] = wv;
            denom += wv * g_ml[(base+c)*256 + row*2 + 1];
        }
        invd[tid] = 1.0f / denom;
    }
    __syncthreads();

    #pragma unroll
    for (int it = 0; it < 4; it++) {
        int idx = tid + it*256;            // 0..1023: 32 rows x 32 float4
        int row = idx >> 5, c4 = idx & 31;
        float4 acc = make_float4(0.f, 0.f, 0.f, 0.f);
        for (int c = 0; c < nch; c++) {
            float4 p = *(const float4*)&g_po[(size_t)(base+c)*16384 + (r0+row)*128 + c4*4];
            float wv = ws[c][row];
            acc.x += wv*p.x; acc.y += wv*p.y; acc.z += wv*p.z; acc.w += wv*p.w;
        }
        float iv = invd[row];
        acc.x *= iv; acc.y *= iv; acc.z *= iv; acc.w *= iv;
        *(float4*)&out[((size_t)bb*T_ + qt*128 + r0 + row)*H_ + c4*4] = acc;
    }
}

// ---------------------------------------------------------------------------
extern "C" void kernel_launch(void* const* d_in, const int* in_sizes, int n_in,
                              void* d_out, int out_size)
{
    const float* x  = (const float*)d_in[0];
    const float* Wq = (const float*)d_in[1];
    const float* bq = (const float*)d_in[2];
    const float* Wk = (const float*)d_in[3];
    const float* bk = (const float*)d_in[4];
    const float* Wv = (const float*)d_in[5];
    const float* bv = (const float*)d_in[6];
    float* out = (float*)d_out;

    convert_kernel<<<1024, 256>>>(x, Wq, Wk, Wv);

    cudaFuncSetAttribute(qkv_kernel,
                         cudaFuncAttributeMaxDynamicSharedMemorySize, QKV_SMEM_BYTES);
    qkv_kernel<<<dim3(M_/64, 3), 256, QKV_SMEM_BYTES>>>(bq, bk, bv);

    cudaFuncSetAttribute(attn_kernel,
                         cudaFuncAttributeMaxDynamicSharedMemorySize, ATT_SMEM_BYTES);
    attn_kernel<<<dim3(34, B_), 256, ATT_SMEM_BYTES>>>(out);

    merge_kernel<<<dim3(11, B_, 4), 256>>>(out);
}